// round 2
// baseline (speedup 1.0000x reference)
#include <cuda_runtime.h>
#include <cstdint>

#define BATCH 2
#define RDIM  64
#define CDIM  2048
#define EDIM  128
#define HEADS 4
#define DHEAD 32
#define NROWS (BATCH*RDIM*CDIM)      // 262144
#define NBR   (BATCH*RDIM)           // 128

typedef unsigned long long u64;

// Scratch (device globals: allocation-free rule)
__device__ float g_q[(size_t)NROWS * EDIM];
__device__ float g_k[(size_t)NROWS * EDIM];
__device__ float g_v[(size_t)NROWS * EDIM];
__device__ float g_ktv[(size_t)NBR * HEADS * DHEAD * DHEAD]; // [br][h][d][e]
__device__ float g_ksum[(size_t)NBR * HEADS * DHEAD];        // [br][h][d]

__device__ __forceinline__ float elu1(float x) {
    return x > 0.f ? x + 1.f : expf(x);
}

// packed dual-fp32 FMA: d.lo += a.lo*b.lo ; d.hi += a.hi*b.hi
__device__ __forceinline__ void ffma2(u64& d, u64 a, u64 b) {
    asm("fma.rn.f32x2 %0, %1, %2, %0;" : "+l"(d) : "l"(a), "l"(b));
}
__device__ __forceinline__ u64 dup32(float v) {
    unsigned u = __float_as_uint(v);
    return (u64)u | ((u64)u << 32);
}
__device__ __forceinline__ float lo32(u64 u) { return __uint_as_float((unsigned)u); }
__device__ __forceinline__ float hi32(u64 u) { return __uint_as_float((unsigned)(u >> 32)); }

// ---------------------------------------------------------------------------
// Kernel A: fused QKV projection. Tile: 128 rows x 128 cols, 512 threads.
// A operand pre-transposed + duplicated (u64 (a,a) pairs) in smem:
//   xd[k][row] -> broadcast LDS.128 in the mainloop (warp-uniform rows).
// smem: xd 128*130 u64 (133120B) + ws 128*128 f (65536B, doubles as staging)
// ---------------------------------------------------------------------------
#define QK_PITCH 130
__global__ __launch_bounds__(512) void qkv_kernel(
    const float* __restrict__ x,
    const float* __restrict__ Wq, const float* __restrict__ bq,
    const float* __restrict__ Wk, const float* __restrict__ bk,
    const float* __restrict__ Wv, const float* __restrict__ bv)
{
    extern __shared__ float sm[];
    u64*   xd = reinterpret_cast<u64*>(sm);        // [128][QK_PITCH]
    float* ws = sm + 128 * QK_PITCH * 2;           // 16384 floats

    const int tid = threadIdx.x;
    const size_t row0 = (size_t)blockIdx.x * 128;

    // stage x tile (row-major, coalesced) into ws region
    {
        const float4* xg = reinterpret_cast<const float4*>(x + row0 * EDIM);
        float4* st4 = reinterpret_cast<float4*>(ws);
#pragma unroll
        for (int i = 0; i < 8; ++i) st4[tid + i * 512] = xg[tid + i * 512];
    }
    __syncthreads();

    // transpose + duplicate into xd[k][row]
    {
        const int w = tid >> 5, l = tid & 31;
#pragma unroll
        for (int r = 0; r < 8; ++r) {
            int row = w * 8 + r;
#pragma unroll
            for (int kb = 0; kb < 4; ++kb) {
                int k = kb * 32 + l;
                xd[k * QK_PITCH + row] = dup32(ws[row * 128 + k]);
            }
        }
    }
    __syncthreads();

    const int ty = tid >> 5;   // 0..15 : rows ty*8 .. ty*8+7 (uniform per warp)
    const int tx = tid & 31;   // cols tx*4 .. tx*4+3

    const float* Wl[3] = {Wq, Wk, Wv};
    const float* Bl[3] = {bq, bk, bv};
    float* Ol[3] = {g_q, g_k, g_v};

    for (int w = 0; w < 3; ++w) {
        if (w) __syncthreads();
        {
            const float4* wg = reinterpret_cast<const float4*>(Wl[w]);
            float4* ws4 = reinterpret_cast<float4*>(ws);
#pragma unroll
            for (int i = 0; i < 8; ++i) ws4[tid + i * 512] = wg[tid + i * 512];
        }
        __syncthreads();

        u64 acc[8][2];
#pragma unroll
        for (int i = 0; i < 8; ++i) { acc[i][0] = 0ull; acc[i][1] = 0ull; }

        const u64* abase = xd + ty * 8;
#pragma unroll 4
        for (int kk = 0; kk < 128; ++kk) {
            ulonglong2 a01 = *reinterpret_cast<const ulonglong2*>(abase + kk * QK_PITCH + 0);
            ulonglong2 a23 = *reinterpret_cast<const ulonglong2*>(abase + kk * QK_PITCH + 2);
            ulonglong2 a45 = *reinterpret_cast<const ulonglong2*>(abase + kk * QK_PITCH + 4);
            ulonglong2 a67 = *reinterpret_cast<const ulonglong2*>(abase + kk * QK_PITCH + 6);
            ulonglong2 b = *reinterpret_cast<const ulonglong2*>(ws + kk * 128 + tx * 4);
            ffma2(acc[0][0], a01.x, b.x); ffma2(acc[0][1], a01.x, b.y);
            ffma2(acc[1][0], a01.y, b.x); ffma2(acc[1][1], a01.y, b.y);
            ffma2(acc[2][0], a23.x, b.x); ffma2(acc[2][1], a23.x, b.y);
            ffma2(acc[3][0], a23.y, b.x); ffma2(acc[3][1], a23.y, b.y);
            ffma2(acc[4][0], a45.x, b.x); ffma2(acc[4][1], a45.x, b.y);
            ffma2(acc[5][0], a45.y, b.x); ffma2(acc[5][1], a45.y, b.y);
            ffma2(acc[6][0], a67.x, b.x); ffma2(acc[6][1], a67.x, b.y);
            ffma2(acc[7][0], a67.y, b.x); ffma2(acc[7][1], a67.y, b.y);
        }

        float4 bb = *reinterpret_cast<const float4*>(&Bl[w][tx * 4]);
        float* outp = Ol[w];
#pragma unroll
        for (int i = 0; i < 8; ++i) {
            float4 r;
            r.x = lo32(acc[i][0]) + bb.x;
            r.y = hi32(acc[i][0]) + bb.y;
            r.z = lo32(acc[i][1]) + bb.z;
            r.w = hi32(acc[i][1]) + bb.w;
            if (w < 2) { r.x = elu1(r.x); r.y = elu1(r.y); r.z = elu1(r.z); r.w = elu1(r.w); }
            *reinterpret_cast<float4*>(&outp[(row0 + ty * 8 + i) * EDIM + tx * 4]) = r;
        }
    }
}

// ---------------------------------------------------------------------------
// Kernel B: per (b,r,h): KtV[d][e] = sum_c k[c,d]*v[c,e]; ksum[d] = sum_c k[c,d]
// ---------------------------------------------------------------------------
__global__ __launch_bounds__(256) void ktv_kernel()
{
    __shared__ float ks[64 * 32];
    __shared__ float vs[64 * 32];

    const int tid = threadIdx.x;
    const int brh = blockIdx.x;
    const int br  = brh >> 2;
    const int h   = brh & 3;
    const size_t base = (size_t)br * CDIM * EDIM + h * DHEAD;

    const int d  = tid >> 3;
    const int j8 = tid & 7;

    float a0 = 0.f, a1 = 0.f, a2 = 0.f, a3 = 0.f, ksum = 0.f;

    for (int c0 = 0; c0 < CDIM; c0 += 64) {
        __syncthreads();
#pragma unroll
        for (int i = 0; i < 2; ++i) {
            int idx = tid + i * 256;
            int c  = idx >> 3;
            int jj = idx & 7;
            const float4* kg = reinterpret_cast<const float4*>(g_k + base + (size_t)(c0 + c) * EDIM) + jj;
            reinterpret_cast<float4*>(ks)[c * 8 + jj] = *kg;
            const float4* vg = reinterpret_cast<const float4*>(g_v + base + (size_t)(c0 + c) * EDIM) + jj;
            reinterpret_cast<float4*>(vs)[c * 8 + jj] = *vg;
        }
        __syncthreads();
#pragma unroll 8
        for (int c = 0; c < 64; ++c) {
            float kd = ks[c * 32 + d];
            float4 vv = reinterpret_cast<const float4*>(vs)[c * 8 + j8];
            a0 += kd * vv.x;
            a1 += kd * vv.y;
            a2 += kd * vv.z;
            a3 += kd * vv.w;
            ksum += kd;
        }
    }

    float4 r; r.x = a0; r.y = a1; r.z = a2; r.w = a3;
    reinterpret_cast<float4*>(g_ktv)[(size_t)brh * 256 + d * 8 + j8] = r;
    if (j8 == 0) g_ksum[(size_t)brh * 32 + d] = ksum;
}

// ---------------------------------------------------------------------------
// Kernel C: z = 1/(q.ksum+eps); attn = (q@KtV)*z; out = attn@Wo + bo
// Both GEMMs with FFMA2. attn results stored straight into dup layout.
// smem: qd 128*66 u64 + ad 128*66 u64 + ws 16384f (staging q) + ktvs 4096f
//       + ksums 128f + zs 256f = 218624 B
// ---------------------------------------------------------------------------
#define OD_PITCH 66
__global__ __launch_bounds__(256) void out_kernel(
    const float* __restrict__ Wo, const float* __restrict__ bo,
    float* __restrict__ out)
{
    extern __shared__ float sm[];
    u64*   qd    = reinterpret_cast<u64*>(sm);            // [128][66]
    u64*   ad    = qd + 128 * OD_PITCH;                   // [128][66]
    float* ws    = reinterpret_cast<float*>(ad + 128 * OD_PITCH); // 16384 f
    float* ktvs  = ws + 16384;                            // 4096 f
    float* ksums = ktvs + 4096;                           // 128 f
    float* zs    = ksums + 128;                           // 256 f

    const int tid = threadIdx.x;
    const int bx  = blockIdx.x;
    const int br  = bx >> 5;
    const int ct  = bx & 31;
    const size_t row0 = (size_t)br * CDIM + ct * 64;

    float* qstage = ws;  // first 8192 floats of ws region

    // loads
    {
        const float4* qg = reinterpret_cast<const float4*>(g_q + row0 * EDIM);
#pragma unroll
        for (int i = 0; i < 8; ++i)
            reinterpret_cast<float4*>(qstage)[tid + i * 256] = qg[tid + i * 256];

        const float4* kg = reinterpret_cast<const float4*>(g_ktv + (size_t)br * 4096);
#pragma unroll
        for (int i = 0; i < 4; ++i)
            reinterpret_cast<float4*>(ktvs)[tid + i * 256] = kg[tid + i * 256];

        if (tid < 32)
            reinterpret_cast<float4*>(ksums)[tid] =
                reinterpret_cast<const float4*>(g_ksum + (size_t)br * 128)[tid];
    }
    __syncthreads();

    // normalizer z (bank-rotated dot)
    {
        int row = tid >> 2;
        int h   = tid & 3;
        const float* qp = qstage + row * 128 + h * 32;
        const float* kp = ksums + h * 32;
        float dot = 0.f;
#pragma unroll
        for (int j = 0; j < 32; ++j) { int d = (j + tid) & 31; dot += qp[d] * kp[d]; }
        zs[row * 4 + h] = 1.f / (dot + 1e-6f);
    }

    // transpose + duplicate q into qd[k][row]
    {
        const int w = tid >> 5, l = tid & 31;
#pragma unroll
        for (int r = 0; r < 8; ++r) {
            int row = w * 8 + r;
#pragma unroll
            for (int kb = 0; kb < 4; ++kb) {
                int k = kb * 32 + l;
                qd[k * OD_PITCH + row] = dup32(qstage[row * 128 + k]);
            }
        }
    }
    __syncthreads();

    // load Wo (overwrites qstage)
    {
        const float4* wg = reinterpret_cast<const float4*>(Wo);
#pragma unroll
        for (int i = 0; i < 16; ++i)
            reinterpret_cast<float4*>(ws)[tid + i * 256] = wg[tid + i * 256];
    }
    __syncthreads();

    const int ty = tid >> 5;
    const int tx = tid & 31;
    const int h  = tx >> 3;

    // attn = (q @ KtV) * z  -> store into ad (dup layout)
    {
        u64 acc[8][2];
#pragma unroll
        for (int i = 0; i < 8; ++i) { acc[i][0] = 0ull; acc[i][1] = 0ull; }

        const u64* qb = qd + ty * 8;
#pragma unroll 4
        for (int dd = 0; dd < 32; ++dd) {
            int k = h * 32 + dd;
            ulonglong2 a01 = *reinterpret_cast<const ulonglong2*>(qb + k * OD_PITCH + 0);
            ulonglong2 a23 = *reinterpret_cast<const ulonglong2*>(qb + k * OD_PITCH + 2);
            ulonglong2 a45 = *reinterpret_cast<const ulonglong2*>(qb + k * OD_PITCH + 4);
            ulonglong2 a67 = *reinterpret_cast<const ulonglong2*>(qb + k * OD_PITCH + 6);
            ulonglong2 b = *reinterpret_cast<const ulonglong2*>(
                ktvs + h * 1024 + dd * 32 + (tx & 7) * 4);
            ffma2(acc[0][0], a01.x, b.x); ffma2(acc[0][1], a01.x, b.y);
            ffma2(acc[1][0], a01.y, b.x); ffma2(acc[1][1], a01.y, b.y);
            ffma2(acc[2][0], a23.x, b.x); ffma2(acc[2][1], a23.x, b.y);
            ffma2(acc[3][0], a23.y, b.x); ffma2(acc[3][1], a23.y, b.y);
            ffma2(acc[4][0], a45.x, b.x); ffma2(acc[4][1], a45.x, b.y);
            ffma2(acc[5][0], a45.y, b.x); ffma2(acc[5][1], a45.y, b.y);
            ffma2(acc[6][0], a67.x, b.x); ffma2(acc[6][1], a67.x, b.y);
            ffma2(acc[7][0], a67.y, b.x); ffma2(acc[7][1], a67.y, b.y);
        }
#pragma unroll
        for (int i = 0; i < 8; ++i) {
            float z = zs[(ty * 8 + i) * 4 + h];
            float c0 = lo32(acc[i][0]) * z;
            float c1 = hi32(acc[i][0]) * z;
            float c2 = lo32(acc[i][1]) * z;
            float c3 = hi32(acc[i][1]) * z;
            int col = tx * 4;
            int row = ty * 8 + i;
            ad[(col + 0) * OD_PITCH + row] = dup32(c0);
            ad[(col + 1) * OD_PITCH + row] = dup32(c1);
            ad[(col + 2) * OD_PITCH + row] = dup32(c2);
            ad[(col + 3) * OD_PITCH + row] = dup32(c3);
        }
    }
    __syncthreads();

    // out = attn @ Wo + bo
    {
        u64 acc[8][2];
#pragma unroll
        for (int i = 0; i < 8; ++i) { acc[i][0] = 0ull; acc[i][1] = 0ull; }

        const u64* ab = ad + ty * 8;
#pragma unroll 4
        for (int kk = 0; kk < 128; ++kk) {
            ulonglong2 a01 = *reinterpret_cast<const ulonglong2*>(ab + kk * OD_PITCH + 0);
            ulonglong2 a23 = *reinterpret_cast<const ulonglong2*>(ab + kk * OD_PITCH + 2);
            ulonglong2 a45 = *reinterpret_cast<const ulonglong2*>(ab + kk * OD_PITCH + 4);
            ulonglong2 a67 = *reinterpret_cast<const ulonglong2*>(ab + kk * OD_PITCH + 6);
            ulonglong2 b = *reinterpret_cast<const ulonglong2*>(ws + kk * 128 + tx * 4);
            ffma2(acc[0][0], a01.x, b.x); ffma2(acc[0][1], a01.x, b.y);
            ffma2(acc[1][0], a01.y, b.x); ffma2(acc[1][1], a01.y, b.y);
            ffma2(acc[2][0], a23.x, b.x); ffma2(acc[2][1], a23.x, b.y);
            ffma2(acc[3][0], a23.y, b.x); ffma2(acc[3][1], a23.y, b.y);
            ffma2(acc[4][0], a45.x, b.x); ffma2(acc[4][1], a45.x, b.y);
            ffma2(acc[5][0], a45.y, b.x); ffma2(acc[5][1], a45.y, b.y);
            ffma2(acc[6][0], a67.x, b.x); ffma2(acc[6][1], a67.x, b.y);
            ffma2(acc[7][0], a67.y, b.x); ffma2(acc[7][1], a67.y, b.y);
        }
        float4 bb = *reinterpret_cast<const float4*>(&bo[tx * 4]);
#pragma unroll
        for (int i = 0; i < 8; ++i) {
            float4 r;
            r.x = lo32(acc[i][0]) + bb.x;
            r.y = hi32(acc[i][0]) + bb.y;
            r.z = lo32(acc[i][1]) + bb.z;
            r.w = hi32(acc[i][1]) + bb.w;
            *reinterpret_cast<float4*>(&out[(row0 + ty * 8 + i) * EDIM + tx * 4]) = r;
        }
    }
}

// ---------------------------------------------------------------------------
extern "C" void kernel_launch(void* const* d_in, const int* in_sizes, int n_in,
                              void* d_out, int out_size)
{
    const float* x  = (const float*)d_in[0];
    const float* Wq = (const float*)d_in[1];
    const float* bq = (const float*)d_in[2];
    const float* Wk = (const float*)d_in[3];
    const float* bk = (const float*)d_in[4];
    const float* Wv = (const float*)d_in[5];
    const float* bv = (const float*)d_in[6];
    const float* Wo = (const float*)d_in[7];
    const float* bo = (const float*)d_in[8];
    float* out = (float*)d_out;

    const int smemA = 128 * QK_PITCH * 8 + 128 * 128 * 4;                  // 198656
    const int smemC = 2 * 128 * OD_PITCH * 8 + (16384 + 4096 + 128 + 256) * 4; // 218624

    cudaFuncSetAttribute(qkv_kernel, cudaFuncAttributeMaxDynamicSharedMemorySize, smemA);
    cudaFuncSetAttribute(out_kernel, cudaFuncAttributeMaxDynamicSharedMemorySize, smemC);

    qkv_kernel<<<NROWS / 128, 512, smemA>>>(x, Wq, bq, Wk, bk, Wv, bv);
    ktv_kernel<<<NBR * HEADS, 256>>>();
    out_kernel<<<NROWS / 64, 256, smemC>>>(Wo, bo, out);
}

// round 4
// speedup vs baseline: 1.6742x; 1.6742x over previous
#include <cuda_runtime.h>
#include <cuda_bf16.h>
#include <cstdint>

#define BATCH 2
#define RDIM  64
#define CDIM  2048
#define EDIM  128
#define HEADS 4
#define DHEAD 32
#define NROWS (BATCH*RDIM*CDIM)      // 262144
#define NBR   (BATCH*RDIM)           // 128

#define PITCH 136                     // bf16 elements per row (bank-conflict-free)

typedef unsigned int u32;

// Scratch (device globals: allocation-free rule)
__device__ float g_q[(size_t)NROWS * EDIM];
__device__ float g_k[(size_t)NROWS * EDIM];
__device__ float g_v[(size_t)NROWS * EDIM];
__device__ float g_ktv[(size_t)NBR * HEADS * DHEAD * DHEAD];
__device__ float g_ksum[(size_t)NBR * HEADS * DHEAD];
// Pre-split transposed weights: [w][hi/lo] Wt[n][k], pitch PITCH, bf16
__device__ __align__(16) __nv_bfloat16 g_wt[4][2][128 * PITCH];

__device__ __forceinline__ float elu1(float x) {
    return x > 0.f ? x + 1.f : expf(x);
}

// mma.sync m16n8k16 row.col f32.bf16.bf16.f32 (portable PTX, works on sm_103)
__device__ __forceinline__ void mma16816(float* d, const u32* a, u32 b0, u32 b1) {
    asm volatile(
        "mma.sync.aligned.m16n8k16.row.col.f32.bf16.bf16.f32 "
        "{%0,%1,%2,%3}, {%4,%5,%6,%7}, {%8,%9}, {%0,%1,%2,%3};"
        : "+f"(d[0]), "+f"(d[1]), "+f"(d[2]), "+f"(d[3])
        : "r"(a[0]), "r"(a[1]), "r"(a[2]), "r"(a[3]), "r"(b0), "r"(b1));
}

// ---------------------------------------------------------------------------
// wprep: W[k][n] fp32 -> Wt[n][k] bf16 hi/lo, pitch PITCH. grid=4 (one per W).
// ---------------------------------------------------------------------------
__global__ __launch_bounds__(256) void wprep_kernel(
    const float* __restrict__ Wq, const float* __restrict__ Wk,
    const float* __restrict__ Wv, const float* __restrict__ Wo)
{
    const float* Wl[4] = {Wq, Wk, Wv, Wo};
    const float* W = Wl[blockIdx.x];
    __nv_bfloat16* hi = g_wt[blockIdx.x][0];
    __nv_bfloat16* lo = g_wt[blockIdx.x][1];
    for (int i = threadIdx.x; i < 128 * 128; i += 256) {
        int k = i >> 7, n = i & 127;
        float v = W[i];
        __nv_bfloat16 h = __float2bfloat16(v);
        __nv_bfloat16 l = __float2bfloat16(v - __bfloat162float(h));
        hi[n * PITCH + k] = h;
        lo[n * PITCH + k] = l;
    }
}

// ---------------------------------------------------------------------------
// Shared 3-pass MMA block: A (rows from arow) x B (cols from ncol0), K=128.
// acc[NT][4]. sa_*/sb_* are smem byte pointers to bf16 [r][k] pitch PITCH.
// ---------------------------------------------------------------------------
template <int NT>
__device__ __forceinline__ void gemm3p(
    const char* sa_hi, const char* sa_lo,
    const char* sb_hi, const char* sb_lo,
    int arow, int ncol0, int lane, float acc[NT][4])
{
    const int g = lane >> 2, c = lane & 3;
#pragma unroll
    for (int k0 = 0; k0 < 128; k0 += 16) {
        const int e0 = ((arow + g) * PITCH + k0 + 2 * c) * 2;
        const int e1 = ((arow + g + 8) * PITCH + k0 + 2 * c) * 2;
        u32 ah[4], al[4];
        ah[0] = *(const u32*)(sa_hi + e0);
        ah[1] = *(const u32*)(sa_hi + e1);
        ah[2] = *(const u32*)(sa_hi + e0 + 16);
        ah[3] = *(const u32*)(sa_hi + e1 + 16);
        al[0] = *(const u32*)(sa_lo + e0);
        al[1] = *(const u32*)(sa_lo + e1);
        al[2] = *(const u32*)(sa_lo + e0 + 16);
        al[3] = *(const u32*)(sa_lo + e1 + 16);
#pragma unroll
        for (int nt = 0; nt < NT; ++nt) {
            const int be = ((ncol0 + nt * 8 + g) * PITCH + k0 + 2 * c) * 2;
            u32 bh0 = *(const u32*)(sb_hi + be);
            u32 bh1 = *(const u32*)(sb_hi + be + 16);
            u32 bl0 = *(const u32*)(sb_lo + be);
            u32 bl1 = *(const u32*)(sb_lo + be + 16);
            mma16816(acc[nt], ah, bh0, bh1);
            mma16816(acc[nt], ah, bl0, bl1);
            mma16816(acc[nt], al, bh0, bh1);
        }
    }
}

// ---------------------------------------------------------------------------
// QKV: per CTA 128 rows; A split once; 3 weights sequential.
// smem: A_hi, A_lo, B_hi, B_lo (each 128*PITCH bf16 = 34816B) + bias 1536B
// ---------------------------------------------------------------------------
#define QA_HI 0
#define QA_LO 34816
#define QB_HI 69632
#define QB_LO 104448
#define QBIAS 139264
#define SMEM_QKV (QBIAS + 3 * 128 * 4)

__global__ __launch_bounds__(256, 1) void qkv_kernel(
    const float* __restrict__ x,
    const float* __restrict__ bq, const float* __restrict__ bk,
    const float* __restrict__ bv)
{
    extern __shared__ char smem[];
    const int tid = threadIdx.x;
    const int wid = tid >> 5;
    const int lane = tid & 31;
    const size_t row0 = (size_t)blockIdx.x * 128;

    float* sbias = (float*)(smem + QBIAS);
    if (tid < 128) {
        sbias[tid]       = bq[tid];
        sbias[128 + tid] = bk[tid];
        sbias[256 + tid] = bv[tid];
    }

    // load x tile, split hi/lo bf16 into [row][k] pitch-PITCH layout
    {
        const float4* xg = reinterpret_cast<const float4*>(x + row0 * EDIM);
#pragma unroll
        for (int i = 0; i < 16; ++i) {
            int idx = tid + i * 256;
            int row = idx >> 5;
            int c4  = (idx & 31) << 2;
            float4 v = xg[idx];
            __nv_bfloat162 h01 = __floats2bfloat162_rn(v.x, v.y);
            __nv_bfloat162 h23 = __floats2bfloat162_rn(v.z, v.w);
            __nv_bfloat162 l01 = __floats2bfloat162_rn(v.x - __low2float(h01),
                                                       v.y - __high2float(h01));
            __nv_bfloat162 l23 = __floats2bfloat162_rn(v.z - __low2float(h23),
                                                       v.w - __high2float(h23));
            int off = (row * PITCH + c4) * 2;
            *(uint2*)(smem + QA_HI + off) = make_uint2(*(u32*)&h01, *(u32*)&h23);
            *(uint2*)(smem + QA_LO + off) = make_uint2(*(u32*)&l01, *(u32*)&l23);
        }
    }

    float* const Ol[3] = {g_q, g_k, g_v};
    const int g = lane >> 2, c = lane & 3;

    for (int w = 0; w < 3; ++w) {
        __syncthreads();   // A ready / B safe to overwrite
        {
            const uint4* gh = (const uint4*)g_wt[w][0];
            const uint4* gl = (const uint4*)g_wt[w][1];
            uint4* sh = (uint4*)(smem + QB_HI);
            uint4* sl = (uint4*)(smem + QB_LO);
            // 128*PITCH*2 bytes = 34816 = 2176 uint4
#pragma unroll
            for (int i = 0; i < 9; ++i) {
                int idx = tid + i * 256;
                if (idx < 2176) { sh[idx] = gh[idx]; sl[idx] = gl[idx]; }
            }
        }
        __syncthreads();

        float acc[16][4];
#pragma unroll
        for (int i = 0; i < 16; ++i)
#pragma unroll
            for (int j = 0; j < 4; ++j) acc[i][j] = 0.f;

        gemm3p<16>(smem + QA_HI, smem + QA_LO, smem + QB_HI, smem + QB_LO,
                   wid * 16, 0, lane, acc);

        // epilogue: bias + (elu+1 for q,k), store fp32
        float* outp = Ol[w];
        const float* bias = sbias + w * 128;
#pragma unroll
        for (int nt = 0; nt < 16; ++nt) {
            int col = nt * 8 + 2 * c;
            float2 bb = *(const float2*)(bias + col);
            float2 r0, r1;
            r0.x = acc[nt][0] + bb.x; r0.y = acc[nt][1] + bb.y;
            r1.x = acc[nt][2] + bb.x; r1.y = acc[nt][3] + bb.y;
            if (w < 2) {
                r0.x = elu1(r0.x); r0.y = elu1(r0.y);
                r1.x = elu1(r1.x); r1.y = elu1(r1.y);
            }
            size_t ra = row0 + wid * 16 + g;
            *(float2*)(outp + ra * EDIM + col)       = r0;
            *(float2*)(outp + (ra + 8) * EDIM + col) = r1;
        }
    }
}

// ---------------------------------------------------------------------------
// ktv: per (b,r,h): KtV[d][e] = sum_c k[c,d]*v[c,e]; ksum[d] = sum_c k[c,d]
// ---------------------------------------------------------------------------
__global__ __launch_bounds__(256) void ktv_kernel()
{
    __shared__ float ks[64 * 32];
    __shared__ float vs[64 * 32];

    const int tid = threadIdx.x;
    const int brh = blockIdx.x;
    const int br  = brh >> 2;
    const int h   = brh & 3;
    const size_t base = (size_t)br * CDIM * EDIM + h * DHEAD;

    const int d  = tid >> 3;
    const int j8 = tid & 7;

    float a0 = 0.f, a1 = 0.f, a2 = 0.f, a3 = 0.f, ksum = 0.f;

    for (int c0 = 0; c0 < CDIM; c0 += 64) {
        __syncthreads();
#pragma unroll
        for (int i = 0; i < 2; ++i) {
            int idx = tid + i * 256;
            int cc = idx >> 3;
            int jj = idx & 7;
            const float4* kg = reinterpret_cast<const float4*>(g_k + base + (size_t)(c0 + cc) * EDIM) + jj;
            reinterpret_cast<float4*>(ks)[cc * 8 + jj] = *kg;
            const float4* vg = reinterpret_cast<const float4*>(g_v + base + (size_t)(c0 + cc) * EDIM) + jj;
            reinterpret_cast<float4*>(vs)[cc * 8 + jj] = *vg;
        }
        __syncthreads();
#pragma unroll 8
        for (int cc = 0; cc < 64; ++cc) {
            float kd = ks[cc * 32 + d];
            float4 vv = reinterpret_cast<const float4*>(vs)[cc * 8 + j8];
            a0 += kd * vv.x;
            a1 += kd * vv.y;
            a2 += kd * vv.z;
            a3 += kd * vv.w;
            ksum += kd;
        }
    }

    float4 r; r.x = a0; r.y = a1; r.z = a2; r.w = a3;
    reinterpret_cast<float4*>(g_ktv)[(size_t)brh * 256 + d * 8 + j8] = r;
    if (j8 == 0) g_ksum[(size_t)brh * 32 + d] = ksum;
}

// ---------------------------------------------------------------------------
// out: z = 1/(q.ksum+eps); attn = (q@KtV)*z (scalar, block-diag);
//      out = attn@Wo + bo via 3-pass MMA. 64 rows per CTA.
// ---------------------------------------------------------------------------
#define OQ    0            // q fp32 [64][128]    32768
#define OKTV  32768        // ktv fp32 [4096]     16384
#define OKS   49152        // ksum [128]f          512
#define OZ    49664        // z [256]f            1024
#define OA_HI 50688        // attn hi bf16        17408
#define OA_LO 68096        // attn lo bf16        17408
#define OW_HI 85504        // Wo hi               34816
#define OW_LO 120320       // Wo lo               34816
#define SMEM_OUT 155136

__global__ __launch_bounds__(256, 1) void out_kernel(
    const float* __restrict__ bo, float* __restrict__ out)
{
    extern __shared__ char smem[];
    float* qs    = (float*)(smem + OQ);
    float* ktvs  = (float*)(smem + OKTV);
    float* ksums = (float*)(smem + OKS);
    float* zs    = (float*)(smem + OZ);

    const int tid = threadIdx.x;
    const int bx  = blockIdx.x;
    const int br  = bx >> 5;
    const int ct  = bx & 31;
    const size_t row0 = (size_t)br * CDIM + ct * 64;

    // loads: q tile, ktv, ksum, Wo hi/lo
    {
        const float4* qg = reinterpret_cast<const float4*>(g_q + row0 * EDIM);
#pragma unroll
        for (int i = 0; i < 8; ++i)
            reinterpret_cast<float4*>(qs)[tid + i * 256] = qg[tid + i * 256];

        const float4* kg = reinterpret_cast<const float4*>(g_ktv + (size_t)br * 4096);
#pragma unroll
        for (int i = 0; i < 4; ++i)
            reinterpret_cast<float4*>(ktvs)[tid + i * 256] = kg[tid + i * 256];

        if (tid < 32)
            reinterpret_cast<float4*>(ksums)[tid] =
                reinterpret_cast<const float4*>(g_ksum + (size_t)br * 128)[tid];

        const uint4* gh = (const uint4*)g_wt[3][0];
        const uint4* gl = (const uint4*)g_wt[3][1];
        uint4* sh = (uint4*)(smem + OW_HI);
        uint4* sl = (uint4*)(smem + OW_LO);
#pragma unroll
        for (int i = 0; i < 9; ++i) {
            int idx = tid + i * 256;
            if (idx < 2176) { sh[idx] = gh[idx]; sl[idx] = gl[idx]; }
        }
    }
    __syncthreads();

    // z per (row, head)
    {
        int row = tid >> 2;
        int h   = tid & 3;
        const float* qp = &qs[row * 128 + h * 32];
        const float* kp = &ksums[h * 32];
        float dot = 0.f;
#pragma unroll
        for (int dd = 0; dd < 32; ++dd) dot += qp[dd] * kp[dd];
        zs[row * 4 + h] = 1.f / (dot + 1e-6f);
    }
    __syncthreads();

    const int ty = tid >> 5;
    const int tx = tid & 31;
    const int hh = tx >> 3;

    // attn = (q @ KtV) * z, scalar; write bf16 hi/lo into OA
    {
        float acc[8][4];
#pragma unroll
        for (int i = 0; i < 8; ++i)
#pragma unroll
            for (int j = 0; j < 4; ++j) acc[i][j] = 0.f;

#pragma unroll 4
        for (int dd = 0; dd < 32; ++dd) {
            float4 b4 = *reinterpret_cast<const float4*>(
                &ktvs[hh * 1024 + dd * 32 + (tx & 7) * 4]);
#pragma unroll
            for (int i = 0; i < 8; ++i) {
                float a = qs[(ty * 8 + i) * 128 + hh * 32 + dd];
                acc[i][0] += a * b4.x;
                acc[i][1] += a * b4.y;
                acc[i][2] += a * b4.z;
                acc[i][3] += a * b4.w;
            }
        }
#pragma unroll
        for (int i = 0; i < 8; ++i) {
            float z = zs[(ty * 8 + i) * 4 + hh];
            float v0 = acc[i][0] * z, v1 = acc[i][1] * z;
            float v2 = acc[i][2] * z, v3 = acc[i][3] * z;
            __nv_bfloat162 h01 = __floats2bfloat162_rn(v0, v1);
            __nv_bfloat162 h23 = __floats2bfloat162_rn(v2, v3);
            __nv_bfloat162 l01 = __floats2bfloat162_rn(v0 - __low2float(h01),
                                                       v1 - __high2float(h01));
            __nv_bfloat162 l23 = __floats2bfloat162_rn(v2 - __low2float(h23),
                                                       v3 - __high2float(h23));
            int row = ty * 8 + i;
            int off = (row * PITCH + tx * 4) * 2;
            *(uint2*)(smem + OA_HI + off) = make_uint2(*(u32*)&h01, *(u32*)&h23);
            *(uint2*)(smem + OA_LO + off) = make_uint2(*(u32*)&l01, *(u32*)&l23);
        }
    }
    __syncthreads();

    // out = attn @ Wo + bo : 8 warps = 4 row-groups x 2 col-halves
    {
        const int wid = tid >> 5;
        const int lane = tid & 31;
        const int g = lane >> 2, c = lane & 3;
        const int arow = (wid & 3) * 16;
        const int ncol0 = (wid >> 2) * 64;

        float acc[8][4];
#pragma unroll
        for (int i = 0; i < 8; ++i)
#pragma unroll
            for (int j = 0; j < 4; ++j) acc[i][j] = 0.f;

        gemm3p<8>(smem + OA_HI, smem + OA_LO, smem + OW_HI, smem + OW_LO,
                  arow, ncol0, lane, acc);

#pragma unroll
        for (int nt = 0; nt < 8; ++nt) {
            int col = ncol0 + nt * 8 + 2 * c;
            float2 bb = *(const float2*)(bo + col);
            float2 r0, r1;
            r0.x = acc[nt][0] + bb.x; r0.y = acc[nt][1] + bb.y;
            r1.x = acc[nt][2] + bb.x; r1.y = acc[nt][3] + bb.y;
            size_t ra = row0 + arow + g;
            *(float2*)(out + ra * EDIM + col)       = r0;
            *(float2*)(out + (ra + 8) * EDIM + col) = r1;
        }
    }
}

// ---------------------------------------------------------------------------
extern "C" void kernel_launch(void* const* d_in, const int* in_sizes, int n_in,
                              void* d_out, int out_size)
{
    const float* x  = (const float*)d_in[0];
    const float* Wq = (const float*)d_in[1];
    const float* bq = (const float*)d_in[2];
    const float* Wk = (const float*)d_in[3];
    const float* bk = (const float*)d_in[4];
    const float* Wv = (const float*)d_in[5];
    const float* bv = (const float*)d_in[6];
    const float* Wo = (const float*)d_in[7];
    const float* bo = (const float*)d_in[8];
    float* out = (float*)d_out;

    cudaFuncSetAttribute(qkv_kernel, cudaFuncAttributeMaxDynamicSharedMemorySize, SMEM_QKV);
    cudaFuncSetAttribute(out_kernel, cudaFuncAttributeMaxDynamicSharedMemorySize, SMEM_OUT);

    wprep_kernel<<<4, 256>>>(Wq, Wk, Wv, Wo);
    qkv_kernel<<<NROWS / 128, 256, SMEM_QKV>>>(x, bq, bk, bv);
    ktv_kernel<<<NBR * HEADS, 256>>>();
    out_kernel<<<NROWS / 64, 256, SMEM_OUT>>>(bo, out);
}

// round 5
// speedup vs baseline: 1.9656x; 1.1741x over previous
#include <cuda_runtime.h>
#include <cuda_bf16.h>
#include <cstdint>

#define BATCH 2
#define RDIM  64
#define CDIM  2048
#define EDIM  128
#define HEADS 4
#define DHEAD 32
#define NROWS (BATCH*RDIM*CDIM)      // 262144
#define NBR   (BATCH*RDIM)           // 128

#define PITCH 136                     // bf16 elements per row

typedef unsigned int u32;

// Scratch (device globals: allocation-free rule)
__device__ float g_q[(size_t)NROWS * EDIM];
__device__ float g_k[(size_t)NROWS * EDIM];
__device__ float g_v[(size_t)NROWS * EDIM];
__device__ float g_ksum[(size_t)NBR * HEADS * DHEAD];
// Per-(b,r) folded matrix G = blockdiag(KtV) @ Wo, split bf16, transposed [n][k]
__device__ __align__(16) __nv_bfloat16 g_G[NBR][2][128 * PITCH];
// Pre-split transposed weights Wq/Wk/Wv: [w][hi/lo] Wt[n][k]
__device__ __align__(16) __nv_bfloat16 g_wt[3][2][128 * PITCH];

__device__ __forceinline__ float elu1(float x) {
    return x > 0.f ? x + 1.f : expf(x);
}

__device__ __forceinline__ void mma16816(float* d, const u32* a, u32 b0, u32 b1) {
    asm volatile(
        "mma.sync.aligned.m16n8k16.row.col.f32.bf16.bf16.f32 "
        "{%0,%1,%2,%3}, {%4,%5,%6,%7}, {%8,%9}, {%0,%1,%2,%3};"
        : "+f"(d[0]), "+f"(d[1]), "+f"(d[2]), "+f"(d[3])
        : "r"(a[0]), "r"(a[1]), "r"(a[2]), "r"(a[3]), "r"(b0), "r"(b1));
}

// 3-pass split GEMM block: rows from arow, cols from ncol0, K=128.
template <int NT>
__device__ __forceinline__ void gemm3p(
    const char* sa_hi, const char* sa_lo,
    const char* sb_hi, const char* sb_lo,
    int arow, int ncol0, int lane, float acc[NT][4])
{
    const int g = lane >> 2, c = lane & 3;
#pragma unroll
    for (int k0 = 0; k0 < 128; k0 += 16) {
        const int e0 = ((arow + g) * PITCH + k0 + 2 * c) * 2;
        const int e1 = ((arow + g + 8) * PITCH + k0 + 2 * c) * 2;
        u32 ah[4], al[4];
        ah[0] = *(const u32*)(sa_hi + e0);
        ah[1] = *(const u32*)(sa_hi + e1);
        ah[2] = *(const u32*)(sa_hi + e0 + 16);
        ah[3] = *(const u32*)(sa_hi + e1 + 16);
        al[0] = *(const u32*)(sa_lo + e0);
        al[1] = *(const u32*)(sa_lo + e1);
        al[2] = *(const u32*)(sa_lo + e0 + 16);
        al[3] = *(const u32*)(sa_lo + e1 + 16);
#pragma unroll
        for (int nt = 0; nt < NT; ++nt) {
            const int be = ((ncol0 + nt * 8 + g) * PITCH + k0 + 2 * c) * 2;
            u32 bh0 = *(const u32*)(sb_hi + be);
            u32 bh1 = *(const u32*)(sb_hi + be + 16);
            u32 bl0 = *(const u32*)(sb_lo + be);
            u32 bl1 = *(const u32*)(sb_lo + be + 16);
            mma16816(acc[nt], ah, bh0, bh1);
            mma16816(acc[nt], ah, bl0, bl1);
            mma16816(acc[nt], al, bh0, bh1);
        }
    }
}

// ---------------------------------------------------------------------------
// wprep: W[k][n] fp32 -> Wt[n][k] bf16 hi/lo. grid=3 (Wq, Wk, Wv).
// ---------------------------------------------------------------------------
__global__ __launch_bounds__(256) void wprep_kernel(
    const float* __restrict__ Wq, const float* __restrict__ Wk,
    const float* __restrict__ Wv)
{
    const float* Wl[3] = {Wq, Wk, Wv};
    const float* W = Wl[blockIdx.x];
    __nv_bfloat16* hi = g_wt[blockIdx.x][0];
    __nv_bfloat16* lo = g_wt[blockIdx.x][1];
    for (int i = threadIdx.x; i < 128 * 128; i += 256) {
        int k = i >> 7, n = i & 127;
        float v = W[i];
        __nv_bfloat16 h = __float2bfloat16(v);
        __nv_bfloat16 l = __float2bfloat16(v - __bfloat162float(h));
        hi[n * PITCH + k] = h;
        lo[n * PITCH + k] = l;
    }
}

// ---------------------------------------------------------------------------
// QKV: 128-row tiles, 512 threads (16 warps), 3 weights sequential.
// smem: A_hi, A_lo, B_hi, B_lo (34816B each) + bias
// ---------------------------------------------------------------------------
#define QA_HI 0
#define QA_LO 34816
#define QB_HI 69632
#define QB_LO 104448
#define QBIAS 139264
#define SMEM_QKV (QBIAS + 3 * 128 * 4)

__global__ __launch_bounds__(512, 1) void qkv_kernel(
    const float* __restrict__ x,
    const float* __restrict__ bq, const float* __restrict__ bk,
    const float* __restrict__ bv)
{
    extern __shared__ char smem[];
    const int tid = threadIdx.x;
    const int wid = tid >> 5;
    const int lane = tid & 31;
    const size_t row0 = (size_t)blockIdx.x * 128;

    float* sbias = (float*)(smem + QBIAS);
    if (tid < 128) {
        sbias[tid]       = bq[tid];
        sbias[128 + tid] = bk[tid];
        sbias[256 + tid] = bv[tid];
    }

    // load x tile, split hi/lo bf16 into [row][k] layout
    {
        const float4* xg = reinterpret_cast<const float4*>(x + row0 * EDIM);
#pragma unroll
        for (int i = 0; i < 8; ++i) {
            int idx = tid + i * 512;
            int row = idx >> 5;
            int c4  = (idx & 31) << 2;
            float4 v = xg[idx];
            __nv_bfloat162 h01 = __floats2bfloat162_rn(v.x, v.y);
            __nv_bfloat162 h23 = __floats2bfloat162_rn(v.z, v.w);
            __nv_bfloat162 l01 = __floats2bfloat162_rn(v.x - __low2float(h01),
                                                       v.y - __high2float(h01));
            __nv_bfloat162 l23 = __floats2bfloat162_rn(v.z - __low2float(h23),
                                                       v.w - __high2float(h23));
            int off = (row * PITCH + c4) * 2;
            *(uint2*)(smem + QA_HI + off) = make_uint2(*(u32*)&h01, *(u32*)&h23);
            *(uint2*)(smem + QA_LO + off) = make_uint2(*(u32*)&l01, *(u32*)&l23);
        }
    }

    float* const Ol[3] = {g_q, g_k, g_v};
    const int g = lane >> 2, c = lane & 3;
    const int arow = (wid & 7) * 16;
    const int ncol0 = (wid >> 3) * 64;

    for (int w = 0; w < 3; ++w) {
        __syncthreads();   // A ready / B safe to overwrite
        {
            const uint4* gh = (const uint4*)g_wt[w][0];
            const uint4* gl = (const uint4*)g_wt[w][1];
            uint4* sh = (uint4*)(smem + QB_HI);
            uint4* sl = (uint4*)(smem + QB_LO);
#pragma unroll
            for (int i = 0; i < 5; ++i) {
                int idx = tid + i * 512;
                if (idx < 2176) { sh[idx] = gh[idx]; sl[idx] = gl[idx]; }
            }
        }
        __syncthreads();

        float acc[8][4];
#pragma unroll
        for (int i = 0; i < 8; ++i)
#pragma unroll
            for (int j = 0; j < 4; ++j) acc[i][j] = 0.f;

        gemm3p<8>(smem + QA_HI, smem + QA_LO, smem + QB_HI, smem + QB_LO,
                  arow, ncol0, lane, acc);

        float* outp = Ol[w];
        const float* bias = sbias + w * 128;
#pragma unroll
        for (int nt = 0; nt < 8; ++nt) {
            int col = ncol0 + nt * 8 + 2 * c;
            float2 bb = *(const float2*)(bias + col);
            float2 r0, r1;
            r0.x = acc[nt][0] + bb.x; r0.y = acc[nt][1] + bb.y;
            r1.x = acc[nt][2] + bb.x; r1.y = acc[nt][3] + bb.y;
            if (w < 2) {
                r0.x = elu1(r0.x); r0.y = elu1(r0.y);
                r1.x = elu1(r1.x); r1.y = elu1(r1.y);
            }
            size_t ra = row0 + arow + g;
            *(float2*)(outp + ra * EDIM + col)       = r0;
            *(float2*)(outp + (ra + 8) * EDIM + col) = r1;
        }
    }
}

// ---------------------------------------------------------------------------
// ktv: per (b,r,h): KtV[d][e] = sum_c k[c,d]*v[c,e]; ksum[d]; then fold:
//      G[d][n] = sum_d' KtV[d][d'] * Wo[h*32+d'][n], store split bf16 [n][k].
// smem pool: main phase ks[2048]+vs[2048]; epilogue ktv_s[1024]+ws[4096].
// ---------------------------------------------------------------------------
__global__ __launch_bounds__(256) void ktv_kernel(const float* __restrict__ Wo)
{
    __shared__ float pool[5120];
    float* ks = pool;            // 2048
    float* vs = pool + 2048;     // 2048

    const int tid = threadIdx.x;
    const int brh = blockIdx.x;
    const int br  = brh >> 2;
    const int h   = brh & 3;
    const size_t base = (size_t)br * CDIM * EDIM + h * DHEAD;

    const int d  = tid >> 3;
    const int j8 = tid & 7;

    float a0 = 0.f, a1 = 0.f, a2 = 0.f, a3 = 0.f, ksum = 0.f;

    for (int c0 = 0; c0 < CDIM; c0 += 64) {
        __syncthreads();
#pragma unroll
        for (int i = 0; i < 2; ++i) {
            int idx = tid + i * 256;
            int cc = idx >> 3;
            int jj = idx & 7;
            const float4* kg = reinterpret_cast<const float4*>(g_k + base + (size_t)(c0 + cc) * EDIM) + jj;
            reinterpret_cast<float4*>(ks)[cc * 8 + jj] = *kg;
            const float4* vg = reinterpret_cast<const float4*>(g_v + base + (size_t)(c0 + cc) * EDIM) + jj;
            reinterpret_cast<float4*>(vs)[cc * 8 + jj] = *vg;
        }
        __syncthreads();
#pragma unroll 8
        for (int cc = 0; cc < 64; ++cc) {
            float kd = ks[cc * 32 + d];
            float4 vv = reinterpret_cast<const float4*>(vs)[cc * 8 + j8];
            a0 += kd * vv.x;
            a1 += kd * vv.y;
            a2 += kd * vv.z;
            a3 += kd * vv.w;
            ksum += kd;
        }
    }

    if (j8 == 0) g_ksum[(size_t)brh * 32 + d] = ksum;

    __syncthreads();   // done with ks/vs

    // transposed KtV into smem: ktv_s[e][d] = KtV[d][e]
    float* ktv_s = pool;          // 1024 floats
    float* ws    = pool + 1024;   // 4096 floats (Wo slice [32][128])
    ktv_s[(j8 * 4 + 0) * 32 + d] = a0;
    ktv_s[(j8 * 4 + 1) * 32 + d] = a1;
    ktv_s[(j8 * 4 + 2) * 32 + d] = a2;
    ktv_s[(j8 * 4 + 3) * 32 + d] = a3;

    // Wo slice: ws[i] = Wo[h*4096 + i] (rows h*32..h*32+31)
    {
        const float4* wg = reinterpret_cast<const float4*>(Wo + h * 4096);
#pragma unroll
        for (int i = 0; i < 4; ++i)
            reinterpret_cast<float4*>(ws)[tid + i * 256] = wg[tid + i * 256];
    }
    __syncthreads();

    // G[d][n]: thread -> n = tid>>1 (0..127), d-range d0 = (tid&1)*16
    {
        const int n  = tid >> 1;
        const int d0 = (tid & 1) * 16;
        float acc[16];
#pragma unroll
        for (int j = 0; j < 16; ++j) acc[j] = 0.f;
#pragma unroll 4
        for (int dp = 0; dp < 32; ++dp) {
            float w = ws[dp * 128 + n];
            const float4* kp = (const float4*)(ktv_s + dp * 32 + d0);
            float4 k0 = kp[0], k1 = kp[1], k2 = kp[2], k3 = kp[3];
            acc[0]  += w * k0.x; acc[1]  += w * k0.y; acc[2]  += w * k0.z; acc[3]  += w * k0.w;
            acc[4]  += w * k1.x; acc[5]  += w * k1.y; acc[6]  += w * k1.z; acc[7]  += w * k1.w;
            acc[8]  += w * k2.x; acc[9]  += w * k2.y; acc[10] += w * k2.z; acc[11] += w * k2.w;
            acc[12] += w * k3.x; acc[13] += w * k3.y; acc[14] += w * k3.z; acc[15] += w * k3.w;
        }
        // split + store 16 consecutive bf16 (32B) per hi/lo
        __nv_bfloat16 hbuf[16], lbuf[16];
#pragma unroll
        for (int j = 0; j < 16; ++j) {
            __nv_bfloat16 hv = __float2bfloat16(acc[j]);
            hbuf[j] = hv;
            lbuf[j] = __float2bfloat16(acc[j] - __bfloat162float(hv));
        }
        int eo = n * PITCH + h * 32 + d0;
        uint4* dh = (uint4*)&g_G[br][0][eo];
        uint4* dl = (uint4*)&g_G[br][1][eo];
        dh[0] = ((uint4*)hbuf)[0]; dh[1] = ((uint4*)hbuf)[1];
        dl[0] = ((uint4*)lbuf)[0]; dl[1] = ((uint4*)lbuf)[1];
    }
}

// ---------------------------------------------------------------------------
// out: z = 1/(q.ksum+eps); q' = q*z (per head); out = q' @ G + bo.
// 64-row tiles, 256 threads, smem ~102.5KB -> 2 CTAs/SM.
// ---------------------------------------------------------------------------
#define OA_HI 0          // 17408
#define OA_LO 17408      // 17408
#define OG_HI 34816      // 34816 (q fp32 staging overlays first 32768B)
#define OG_LO 69632      // 34816
#define OKS   104448     // 512
#define SMEM_OUT (OKS + 512)

__global__ __launch_bounds__(256, 2) void out_kernel(
    const float* __restrict__ bo, float* __restrict__ out)
{
    extern __shared__ char smem[];
    float* qs    = (float*)(smem + OG_HI);   // staging, overwritten by G later
    float* ksums = (float*)(smem + OKS);

    const int tid = threadIdx.x;
    const int bx  = blockIdx.x;
    const int br  = bx >> 5;           // 32 tiles of 64 rows per (b,r)
    const int ct  = bx & 31;
    const size_t row0 = (size_t)br * CDIM + ct * 64;

    // load q tile fp32 + ksum
    {
        const float4* qg = reinterpret_cast<const float4*>(g_q + row0 * EDIM);
#pragma unroll
        for (int i = 0; i < 8; ++i)
            reinterpret_cast<float4*>(qs)[tid + i * 256] = qg[tid + i * 256];
        if (tid < 32)
            reinterpret_cast<float4*>(ksums)[tid] =
                reinterpret_cast<const float4*>(g_ksum + (size_t)br * 128)[tid];
    }
    __syncthreads();

    // z per (row, head); build A = split(q * z)
    {
        const int row = tid >> 2;
        const int h   = tid & 3;
        const float* qrow = qs + row * 128 + h * 32;
        const float* ksp  = ksums + h * 32;
        const int rot = (row * 4) & 31;
        float qv[32];
        float dot = 0.f;
#pragma unroll
        for (int i = 0; i < 32; ++i) {
            int ii = (i + rot) & 31;
            qv[i] = qrow[ii];
            dot += qv[i] * ksp[ii];
        }
        float z = 1.f / (dot + 1e-6f);
        __nv_bfloat16* ah = (__nv_bfloat16*)(smem + OA_HI);
        __nv_bfloat16* al = (__nv_bfloat16*)(smem + OA_LO);
#pragma unroll
        for (int i = 0; i < 32; ++i) {
            int ii = (i + rot) & 31;
            float v = qv[i] * z;
            __nv_bfloat16 hv = __float2bfloat16(v);
            int eo = row * PITCH + h * 32 + ii;
            ah[eo] = hv;
            al[eo] = __float2bfloat16(v - __bfloat162float(hv));
        }
    }
    __syncthreads();   // A done, qs reads done -> load G over staging

    {
        const uint4* gh = (const uint4*)g_G[br][0];
        const uint4* gl = (const uint4*)g_G[br][1];
        uint4* sh = (uint4*)(smem + OG_HI);
        uint4* sl = (uint4*)(smem + OG_LO);
#pragma unroll
        for (int i = 0; i < 9; ++i) {
            int idx = tid + i * 256;
            if (idx < 2176) { sh[idx] = gh[idx]; sl[idx] = gl[idx]; }
        }
    }
    __syncthreads();

    // out = q' @ G + bo : 8 warps = 4 row-groups x 2 col-halves
    {
        const int wid = tid >> 5;
        const int lane = tid & 31;
        const int g = lane >> 2, c = lane & 3;
        const int arow = (wid & 3) * 16;
        const int ncol0 = (wid >> 2) * 64;

        float acc[8][4];
#pragma unroll
        for (int i = 0; i < 8; ++i)
#pragma unroll
            for (int j = 0; j < 4; ++j) acc[i][j] = 0.f;

        gemm3p<8>(smem + OA_HI, smem + OA_LO, smem + OG_HI, smem + OG_LO,
                  arow, ncol0, lane, acc);

#pragma unroll
        for (int nt = 0; nt < 8; ++nt) {
            int col = ncol0 + nt * 8 + 2 * c;
            float2 bb = *(const float2*)(bo + col);
            float2 r0, r1;
            r0.x = acc[nt][0] + bb.x; r0.y = acc[nt][1] + bb.y;
            r1.x = acc[nt][2] + bb.x; r1.y = acc[nt][3] + bb.y;
            size_t ra = row0 + arow + g;
            *(float2*)(out + ra * EDIM + col)       = r0;
            *(float2*)(out + (ra + 8) * EDIM + col) = r1;
        }
    }
}

// ---------------------------------------------------------------------------
extern "C" void kernel_launch(void* const* d_in, const int* in_sizes, int n_in,
                              void* d_out, int out_size)
{
    const float* x  = (const float*)d_in[0];
    const float* Wq = (const float*)d_in[1];
    const float* bq = (const float*)d_in[2];
    const float* Wk = (const float*)d_in[3];
    const float* bk = (const float*)d_in[4];
    const float* Wv = (const float*)d_in[5];
    const float* bv = (const float*)d_in[6];
    const float* Wo = (const float*)d_in[7];
    const float* bo = (const float*)d_in[8];
    float* out = (float*)d_out;

    cudaFuncSetAttribute(qkv_kernel, cudaFuncAttributeMaxDynamicSharedMemorySize, SMEM_QKV);
    cudaFuncSetAttribute(out_kernel, cudaFuncAttributeMaxDynamicSharedMemorySize, SMEM_OUT);

    wprep_kernel<<<3, 256>>>(Wq, Wk, Wv);
    qkv_kernel<<<NROWS / 128, 512, SMEM_QKV>>>(x, bq, bk, bv);
    ktv_kernel<<<NBR * HEADS, 256>>>(Wo);
    out_kernel<<<NROWS / 64, 256, SMEM_OUT>>>(bo, out);
}

// round 6
// speedup vs baseline: 2.5470x; 1.2958x over previous
#include <cuda_runtime.h>
#include <cuda_bf16.h>
#include <cstdint>

#define BATCH 2
#define RDIM  64
#define CDIM  2048
#define EDIM  128
#define HEADS 4
#define DHEAD 32
#define NROWS (BATCH*RDIM*CDIM)      // 262144
#define NBR   (BATCH*RDIM)           // 128
#define NCTA  (NROWS/128)            // 2048 qkv CTAs
#define PART_STRIDE 4224             // 4*32*32 ktv + 128 ksum floats per CTA

#define PITCH 136                     // bf16 elements per row

typedef unsigned int u32;

// Scratch (device globals: allocation-free rule)
__device__ float g_q[(size_t)NROWS * EDIM];
__device__ float g_ksum[(size_t)NBR * HEADS * DHEAD];
__device__ __align__(16) float g_part[(size_t)NCTA * PART_STRIDE];
// Per-(b,r) folded matrix G = blockdiag(KtV) @ Wo, split bf16, transposed [n][k]
__device__ __align__(16) __nv_bfloat16 g_G[NBR][2][128 * PITCH];
// Pre-split transposed weights Wq/Wk/Wv: [w][hi/lo] Wt[n][k]
__device__ __align__(16) __nv_bfloat16 g_wt[3][2][128 * PITCH];

__device__ __forceinline__ float elu1(float x) {
    return x > 0.f ? x + 1.f : expf(x);
}

__device__ __forceinline__ void mma16816(float* d, const u32* a, u32 b0, u32 b1) {
    asm volatile(
        "mma.sync.aligned.m16n8k16.row.col.f32.bf16.bf16.f32 "
        "{%0,%1,%2,%3}, {%4,%5,%6,%7}, {%8,%9}, {%0,%1,%2,%3};"
        : "+f"(d[0]), "+f"(d[1]), "+f"(d[2]), "+f"(d[3])
        : "r"(a[0]), "r"(a[1]), "r"(a[2]), "r"(a[3]), "r"(b0), "r"(b1));
}

__device__ __forceinline__ void ldsm_x4_t(u32* r, u32 addr) {
    asm volatile("ldmatrix.sync.aligned.m8n8.x4.trans.shared.b16 {%0,%1,%2,%3}, [%4];"
        : "=r"(r[0]), "=r"(r[1]), "=r"(r[2]), "=r"(r[3]) : "r"(addr));
}

__device__ __forceinline__ uint32_t smem_u32(const void* p) {
    uint32_t a;
    asm("{ .reg .u64 t; cvta.to.shared.u64 t, %1; cvt.u32.u64 %0, t; }" : "=r"(a) : "l"(p));
    return a;
}

__device__ __forceinline__ u32 pack_bf2(float x, float y) {
    __nv_bfloat162 p = __floats2bfloat162_rn(x, y);
    return *(u32*)&p;
}

// 3-pass split GEMM block (scalar LDS fragments, proven): K=128.
template <int NT>
__device__ __forceinline__ void gemm3p(
    const char* sa_hi, const char* sa_lo,
    const char* sb_hi, const char* sb_lo,
    int arow, int ncol0, int lane, float acc[NT][4])
{
    const int g = lane >> 2, c = lane & 3;
#pragma unroll
    for (int k0 = 0; k0 < 128; k0 += 16) {
        const int e0 = ((arow + g) * PITCH + k0 + 2 * c) * 2;
        const int e1 = ((arow + g + 8) * PITCH + k0 + 2 * c) * 2;
        u32 ah[4], al[4];
        ah[0] = *(const u32*)(sa_hi + e0);
        ah[1] = *(const u32*)(sa_hi + e1);
        ah[2] = *(const u32*)(sa_hi + e0 + 16);
        ah[3] = *(const u32*)(sa_hi + e1 + 16);
        al[0] = *(const u32*)(sa_lo + e0);
        al[1] = *(const u32*)(sa_lo + e1);
        al[2] = *(const u32*)(sa_lo + e0 + 16);
        al[3] = *(const u32*)(sa_lo + e1 + 16);
#pragma unroll
        for (int nt = 0; nt < NT; ++nt) {
            const int be = ((ncol0 + nt * 8 + g) * PITCH + k0 + 2 * c) * 2;
            u32 bh0 = *(const u32*)(sb_hi + be);
            u32 bh1 = *(const u32*)(sb_hi + be + 16);
            u32 bl0 = *(const u32*)(sb_lo + be);
            u32 bl1 = *(const u32*)(sb_lo + be + 16);
            mma16816(acc[nt], ah, bh0, bh1);
            mma16816(acc[nt], ah, bl0, bl1);
            mma16816(acc[nt], al, bh0, bh1);
        }
    }
}

// ---------------------------------------------------------------------------
// wprep: W[k][n] fp32 -> Wt[n][k] bf16 hi/lo. grid=3 (Wq, Wk, Wv).
// ---------------------------------------------------------------------------
__global__ __launch_bounds__(256) void wprep_kernel(
    const float* __restrict__ Wq, const float* __restrict__ Wk,
    const float* __restrict__ Wv)
{
    const float* Wl[3] = {Wq, Wk, Wv};
    const float* W = Wl[blockIdx.x];
    __nv_bfloat16* hi = g_wt[blockIdx.x][0];
    __nv_bfloat16* lo = g_wt[blockIdx.x][1];
    for (int i = threadIdx.x; i < 128 * 128; i += 256) {
        int k = i >> 7, n = i & 127;
        float v = W[i];
        __nv_bfloat16 h = __float2bfloat16(v);
        __nv_bfloat16 l = __float2bfloat16(v - __bfloat162float(h));
        hi[n * PITCH + k] = h;
        lo[n * PITCH + k] = l;
    }
}

// ---------------------------------------------------------------------------
// QKV + fused per-CTA KtV partial. 128-row tiles, 512 threads.
// smem: QA(x split) | QB(weights, then v split) | KS(k split) | bias | ksum slots
// ---------------------------------------------------------------------------
#define QA_HI 0
#define QA_LO 34816
#define QB_HI 69632
#define QB_LO 104448
#define KS_HI 139264
#define KS_LO 174080
#define QBIAS 208896
#define QKSUM 210432            // float[8][128]
#define SMEM_QKV (QKSUM + 8 * 128 * 4)

__global__ __launch_bounds__(512, 1) void qkv_kernel(
    const float* __restrict__ x,
    const float* __restrict__ bq, const float* __restrict__ bk,
    const float* __restrict__ bv)
{
    extern __shared__ char smem[];
    const u32 sb = smem_u32(smem);
    const int tid = threadIdx.x;
    const int wid = tid >> 5;
    const int lane = tid & 31;
    const int g = lane >> 2, c = lane & 3;
    const size_t row0 = (size_t)blockIdx.x * 128;

    float* sbias = (float*)(smem + QBIAS);
    float* sksum = (float*)(smem + QKSUM);
    if (tid < 128) {
        sbias[tid]       = bq[tid];
        sbias[128 + tid] = bk[tid];
        sbias[256 + tid] = bv[tid];
    }

    // load x tile, split hi/lo bf16 into [row][k] layout
    {
        const float4* xg = reinterpret_cast<const float4*>(x + row0 * EDIM);
#pragma unroll
        for (int i = 0; i < 8; ++i) {
            int idx = tid + i * 512;
            int row = idx >> 5;
            int c4  = (idx & 31) << 2;
            float4 v = xg[idx];
            u32 h01 = pack_bf2(v.x, v.y);
            u32 h23 = pack_bf2(v.z, v.w);
            float hx = __bfloat162float(*(__nv_bfloat16*)&h01);
            float hy = __bfloat162float(((__nv_bfloat16*)&h01)[1]);
            float hz = __bfloat162float(*(__nv_bfloat16*)&h23);
            float hw = __bfloat162float(((__nv_bfloat16*)&h23)[1]);
            u32 l01 = pack_bf2(v.x - hx, v.y - hy);
            u32 l23 = pack_bf2(v.z - hz, v.w - hw);
            int off = (row * PITCH + c4) * 2;
            *(uint2*)(smem + QA_HI + off) = make_uint2(h01, h23);
            *(uint2*)(smem + QA_LO + off) = make_uint2(l01, l23);
        }
    }

    const int arow = (wid & 7) * 16;
    const int ncol0 = (wid >> 3) * 64;
    const int aw = wid & 7;

    for (int w = 0; w < 3; ++w) {
        __syncthreads();   // x/QB readers done -> safe to (re)load QB
        {
            const uint4* gh = (const uint4*)g_wt[w][0];
            const uint4* gl = (const uint4*)g_wt[w][1];
            uint4* sh = (uint4*)(smem + QB_HI);
            uint4* sl = (uint4*)(smem + QB_LO);
#pragma unroll
            for (int i = 0; i < 5; ++i) {
                int idx = tid + i * 512;
                if (idx < 2176) { sh[idx] = gh[idx]; sl[idx] = gl[idx]; }
            }
        }
        __syncthreads();

        float acc[8][4];
#pragma unroll
        for (int i = 0; i < 8; ++i)
#pragma unroll
            for (int j = 0; j < 4; ++j) acc[i][j] = 0.f;

        gemm3p<8>(smem + QA_HI, smem + QA_LO, smem + QB_HI, smem + QB_LO,
                  arow, ncol0, lane, acc);

        const float* bias = sbias + w * 128;

        if (w == 0) {
            // q: bias + elu, store fp32 to global
#pragma unroll
            for (int nt = 0; nt < 8; ++nt) {
                int col = ncol0 + nt * 8 + 2 * c;
                float2 bb = *(const float2*)(bias + col);
                float2 r0, r1;
                r0.x = elu1(acc[nt][0] + bb.x); r0.y = elu1(acc[nt][1] + bb.y);
                r1.x = elu1(acc[nt][2] + bb.x); r1.y = elu1(acc[nt][3] + bb.y);
                size_t ra = row0 + arow + g;
                *(float2*)(g_q + ra * EDIM + col)       = r0;
                *(float2*)(g_q + (ra + 8) * EDIM + col) = r1;
            }
        } else if (w == 1) {
            // k: bias + elu, split into KS smem; ksum partials via shuffles
#pragma unroll
            for (int nt = 0; nt < 8; ++nt) {
                int col = ncol0 + nt * 8 + 2 * c;
                float2 bb = *(const float2*)(bias + col);
                float k0x = elu1(acc[nt][0] + bb.x), k0y = elu1(acc[nt][1] + bb.y);
                float k1x = elu1(acc[nt][2] + bb.x), k1y = elu1(acc[nt][3] + bb.y);
                u32 h0 = pack_bf2(k0x, k0y);
                u32 h1 = pack_bf2(k1x, k1y);
                float h0x = __bfloat162float(*(__nv_bfloat16*)&h0);
                float h0y = __bfloat162float(((__nv_bfloat16*)&h0)[1]);
                float h1x = __bfloat162float(*(__nv_bfloat16*)&h1);
                float h1y = __bfloat162float(((__nv_bfloat16*)&h1)[1]);
                u32 l0 = pack_bf2(k0x - h0x, k0y - h0y);
                u32 l1 = pack_bf2(k1x - h1x, k1y - h1y);
                int o0 = ((arow + g) * PITCH + col) * 2;
                int o1 = ((arow + g + 8) * PITCH + col) * 2;
                *(u32*)(smem + KS_HI + o0) = h0;
                *(u32*)(smem + KS_LO + o0) = l0;
                *(u32*)(smem + KS_HI + o1) = h1;
                *(u32*)(smem + KS_LO + o1) = l1;
                // ksum partial for cols col, col+1 over this warp's 16 rows
                float s0 = k0x + k1x;
                float s1 = k0y + k1y;
                s0 += __shfl_xor_sync(0xffffffffu, s0, 16);
                s0 += __shfl_xor_sync(0xffffffffu, s0, 8);
                s0 += __shfl_xor_sync(0xffffffffu, s0, 4);
                s1 += __shfl_xor_sync(0xffffffffu, s1, 16);
                s1 += __shfl_xor_sync(0xffffffffu, s1, 8);
                s1 += __shfl_xor_sync(0xffffffffu, s1, 4);
                if (lane < 4) {
                    sksum[aw * 128 + col]     = s0;
                    sksum[aw * 128 + col + 1] = s1;
                }
            }
        } else {
            // v: bias only; hold, then write split into QB after all mma done
#pragma unroll
            for (int nt = 0; nt < 8; ++nt) {
                int col = ncol0 + nt * 8 + 2 * c;
                float2 bb = *(const float2*)(bias + col);
                acc[nt][0] += bb.x; acc[nt][1] += bb.y;
                acc[nt][2] += bb.x; acc[nt][3] += bb.y;
            }
            __syncthreads();   // everyone done reading QB (Wv)
#pragma unroll
            for (int nt = 0; nt < 8; ++nt) {
                int col = ncol0 + nt * 8 + 2 * c;
                u32 h0 = pack_bf2(acc[nt][0], acc[nt][1]);
                u32 h1 = pack_bf2(acc[nt][2], acc[nt][3]);
                float h0x = __bfloat162float(*(__nv_bfloat16*)&h0);
                float h0y = __bfloat162float(((__nv_bfloat16*)&h0)[1]);
                float h1x = __bfloat162float(*(__nv_bfloat16*)&h1);
                float h1y = __bfloat162float(((__nv_bfloat16*)&h1)[1]);
                u32 l0 = pack_bf2(acc[nt][0] - h0x, acc[nt][1] - h0y);
                u32 l1 = pack_bf2(acc[nt][2] - h1x, acc[nt][3] - h1y);
                int o0 = ((arow + g) * PITCH + col) * 2;
                int o1 = ((arow + g + 8) * PITCH + col) * 2;
                *(u32*)(smem + QB_HI + o0) = h0;
                *(u32*)(smem + QB_LO + o0) = l0;
                *(u32*)(smem + QB_HI + o1) = h1;
                *(u32*)(smem + QB_LO + o1) = l1;
            }
        }
    }

    // ksum partial: reduce 8 slots -> g_part (deterministic)
    // (sksum written in w=1 epilogue; all syncs since then... need one now)
    __syncthreads();   // v-split writes + sksum complete

    if (tid < 128) {
        float s = 0.f;
#pragma unroll
        for (int i = 0; i < 8; ++i) s += sksum[i * 128 + tid];
        g_part[(size_t)blockIdx.x * PART_STRIDE + 4096 + tid] = s;
    }

    // ---- KtV partial phase: per warp (h, mtile, npair) ----
    {
        const int h  = wid & 3;
        const int mt = (wid >> 2) & 1;
        const int np = wid >> 3;
        const int d0 = h * 32 + mt * 16;
        const int e0 = h * 32 + np * 16;

        const u32 a_roff = (u32)(((lane & 7) + ((lane & 16) ? 8 : 0)) * (PITCH * 2));
        const u32 a_coff = (u32)((d0 + ((lane & 8) ? 8 : 0)) * 2);
        const u32 b_roff = (u32)(((lane & 7) + ((lane & 8) ? 8 : 0)) * (PITCH * 2));
        const u32 b_coff = (u32)((e0 + ((lane & 16) ? 8 : 0)) * 2);
        const u32 a_hi = sb + KS_HI + a_roff + a_coff;
        const u32 a_lo = sb + KS_LO + a_roff + a_coff;
        const u32 b_hi = sb + QB_HI + b_roff + b_coff;
        const u32 b_lo = sb + QB_LO + b_roff + b_coff;

        float acc[2][4];
#pragma unroll
        for (int i = 0; i < 2; ++i)
#pragma unroll
            for (int j = 0; j < 4; ++j) acc[i][j] = 0.f;

#pragma unroll
        for (int c0 = 0; c0 < 128; c0 += 16) {
            u32 off = (u32)(c0 * (PITCH * 2));
            u32 ah[4], al[4], bh[4], bl[4];
            ldsm_x4_t(ah, a_hi + off);
            ldsm_x4_t(al, a_lo + off);
            ldsm_x4_t(bh, b_hi + off);
            ldsm_x4_t(bl, b_lo + off);
            mma16816(acc[0], ah, bh[0], bh[1]);
            mma16816(acc[0], ah, bl[0], bl[1]);
            mma16816(acc[0], al, bh[0], bh[1]);
            mma16816(acc[1], ah, bh[2], bh[3]);
            mma16816(acc[1], ah, bl[2], bl[3]);
            mma16816(acc[1], al, bh[2], bh[3]);
        }

        float* dst = g_part + (size_t)blockIdx.x * PART_STRIDE + h * 1024;
#pragma unroll
        for (int nt = 0; nt < 2; ++nt) {
            int d_lo = mt * 16 + g;
            int e_lo = np * 16 + nt * 8 + 2 * c;
            *(float2*)&dst[d_lo * 32 + e_lo]       = make_float2(acc[nt][0], acc[nt][1]);
            *(float2*)&dst[(d_lo + 8) * 32 + e_lo] = make_float2(acc[nt][2], acc[nt][3]);
        }
    }
}

// ---------------------------------------------------------------------------
// fold: per (br,h): reduce 16 CTA partials -> KtV; ksum (h==0);
//       G[d][n] = sum_d' KtV[d][d']*Wo[h*32+d'][n] -> split bf16 [n][k].
// ---------------------------------------------------------------------------
__global__ __launch_bounds__(256) void fold_kernel(const float* __restrict__ Wo)
{
    __shared__ float ktv_s[1024];   // [e][d]
    __shared__ float ws[4096];      // Wo slice [32][128]

    const int tid = threadIdx.x;
    const int br  = blockIdx.x >> 2;
    const int h   = blockIdx.x & 3;
    const float* base = g_part + (size_t)br * 16 * PART_STRIDE;

    // reduce KtV (4 values per thread)
    {
        float v0 = 0.f, v1 = 0.f, v2 = 0.f, v3 = 0.f;
#pragma unroll 4
        for (int i = 0; i < 16; ++i) {
            float4 p = *(const float4*)(base + (size_t)i * PART_STRIDE + h * 1024 + tid * 4);
            v0 += p.x; v1 += p.y; v2 += p.z; v3 += p.w;
        }
        int d = tid >> 3, e0 = (tid & 7) * 4;
        ktv_s[(e0 + 0) * 32 + d] = v0;
        ktv_s[(e0 + 1) * 32 + d] = v1;
        ktv_s[(e0 + 2) * 32 + d] = v2;
        ktv_s[(e0 + 3) * 32 + d] = v3;
    }

    // ksum reduce (h==0 blocks)
    if (h == 0 && tid < 128) {
        float s = 0.f;
#pragma unroll 4
        for (int i = 0; i < 16; ++i)
            s += base[(size_t)i * PART_STRIDE + 4096 + tid];
        g_ksum[(size_t)br * 128 + tid] = s;
    }

    // Wo slice rows h*32 .. h*32+31
    {
        const float4* wg = reinterpret_cast<const float4*>(Wo + h * 4096);
#pragma unroll
        for (int i = 0; i < 4; ++i)
            reinterpret_cast<float4*>(ws)[tid + i * 256] = wg[tid + i * 256];
    }
    __syncthreads();

    // G: thread -> n = tid>>1, d-range d0 = (tid&1)*16
    {
        const int n  = tid >> 1;
        const int d0 = (tid & 1) * 16;
        float acc[16];
#pragma unroll
        for (int j = 0; j < 16; ++j) acc[j] = 0.f;
#pragma unroll 4
        for (int dp = 0; dp < 32; ++dp) {
            float w = ws[dp * 128 + n];
            const float4* kp = (const float4*)(ktv_s + dp * 32 + d0);
            float4 k0 = kp[0], k1 = kp[1], k2 = kp[2], k3 = kp[3];
            acc[0]  += w * k0.x; acc[1]  += w * k0.y; acc[2]  += w * k0.z; acc[3]  += w * k0.w;
            acc[4]  += w * k1.x; acc[5]  += w * k1.y; acc[6]  += w * k1.z; acc[7]  += w * k1.w;
            acc[8]  += w * k2.x; acc[9]  += w * k2.y; acc[10] += w * k2.z; acc[11] += w * k2.w;
            acc[12] += w * k3.x; acc[13] += w * k3.y; acc[14] += w * k3.z; acc[15] += w * k3.w;
        }
        __nv_bfloat16 hbuf[16], lbuf[16];
#pragma unroll
        for (int j = 0; j < 16; ++j) {
            __nv_bfloat16 hv = __float2bfloat16(acc[j]);
            hbuf[j] = hv;
            lbuf[j] = __float2bfloat16(acc[j] - __bfloat162float(hv));
        }
        int eo = n * PITCH + h * 32 + d0;
        uint4* dh = (uint4*)&g_G[br][0][eo];
        uint4* dl = (uint4*)&g_G[br][1][eo];
        dh[0] = ((uint4*)hbuf)[0]; dh[1] = ((uint4*)hbuf)[1];
        dl[0] = ((uint4*)lbuf)[0]; dl[1] = ((uint4*)lbuf)[1];
    }
}

// ---------------------------------------------------------------------------
// out: z = 1/(q.ksum+eps); q' = q*z; out = q' @ G + bo.  (unchanged from R5)
// ---------------------------------------------------------------------------
#define OA_HI 0
#define OA_LO 17408
#define OG_HI 34816
#define OG_LO 69632
#define OKS   104448
#define SMEM_OUT (OKS + 512)

__global__ __launch_bounds__(256, 2) void out_kernel(
    const float* __restrict__ bo, float* __restrict__ out)
{
    extern __shared__ char smem[];
    float* qs    = (float*)(smem + OG_HI);
    float* ksums = (float*)(smem + OKS);

    const int tid = threadIdx.x;
    const int bx  = blockIdx.x;
    const int br  = bx >> 5;
    const int ct  = bx & 31;
    const size_t row0 = (size_t)br * CDIM + ct * 64;

    {
        const float4* qg = reinterpret_cast<const float4*>(g_q + row0 * EDIM);
#pragma unroll
        for (int i = 0; i < 8; ++i)
            reinterpret_cast<float4*>(qs)[tid + i * 256] = qg[tid + i * 256];
        if (tid < 32)
            reinterpret_cast<float4*>(ksums)[tid] =
                reinterpret_cast<const float4*>(g_ksum + (size_t)br * 128)[tid];
    }
    __syncthreads();

    {
        const int row = tid >> 2;
        const int h   = tid & 3;
        const float* qrow = qs + row * 128 + h * 32;
        const float* ksp  = ksums + h * 32;
        const int rot = (row * 4) & 31;
        float qv[32];
        float dot = 0.f;
#pragma unroll
        for (int i = 0; i < 32; ++i) {
            int ii = (i + rot) & 31;
            qv[i] = qrow[ii];
            dot += qv[i] * ksp[ii];
        }
        float z = 1.f / (dot + 1e-6f);
        __nv_bfloat16* ah = (__nv_bfloat16*)(smem + OA_HI);
        __nv_bfloat16* al = (__nv_bfloat16*)(smem + OA_LO);
#pragma unroll
        for (int i = 0; i < 32; ++i) {
            int ii = (i + rot) & 31;
            float v = qv[i] * z;
            __nv_bfloat16 hv = __float2bfloat16(v);
            int eo = row * PITCH + h * 32 + ii;
            ah[eo] = hv;
            al[eo] = __float2bfloat16(v - __bfloat162float(hv));
        }
    }
    __syncthreads();

    {
        const uint4* gh = (const uint4*)g_G[br][0];
        const uint4* gl = (const uint4*)g_G[br][1];
        uint4* sh = (uint4*)(smem + OG_HI);
        uint4* sl = (uint4*)(smem + OG_LO);
#pragma unroll
        for (int i = 0; i < 9; ++i) {
            int idx = tid + i * 256;
            if (idx < 2176) { sh[idx] = gh[idx]; sl[idx] = gl[idx]; }
        }
    }
    __syncthreads();

    {
        const int wid = tid >> 5;
        const int lane = tid & 31;
        const int g = lane >> 2, c = lane & 3;
        const int arow = (wid & 3) * 16;
        const int ncol0 = (wid >> 2) * 64;

        float acc[8][4];
#pragma unroll
        for (int i = 0; i < 8; ++i)
#pragma unroll
            for (int j = 0; j < 4; ++j) acc[i][j] = 0.f;

        gemm3p<8>(smem + OA_HI, smem + OA_LO, smem + OG_HI, smem + OG_LO,
                  arow, ncol0, lane, acc);

#pragma unroll
        for (int nt = 0; nt < 8; ++nt) {
            int col = ncol0 + nt * 8 + 2 * c;
            float2 bb = *(const float2*)(bo + col);
            float2 r0, r1;
            r0.x = acc[nt][0] + bb.x; r0.y = acc[nt][1] + bb.y;
            r1.x = acc[nt][2] + bb.x; r1.y = acc[nt][3] + bb.y;
            size_t ra = row0 + arow + g;
            *(float2*)(out + ra * EDIM + col)       = r0;
            *(float2*)(out + (ra + 8) * EDIM + col) = r1;
        }
    }
}

// ---------------------------------------------------------------------------
extern "C" void kernel_launch(void* const* d_in, const int* in_sizes, int n_in,
                              void* d_out, int out_size)
{
    const float* x  = (const float*)d_in[0];
    const float* Wq = (const float*)d_in[1];
    const float* bq = (const float*)d_in[2];
    const float* Wk = (const float*)d_in[3];
    const float* bk = (const float*)d_in[4];
    const float* Wv = (const float*)d_in[5];
    const float* bv = (const float*)d_in[6];
    const float* Wo = (const float*)d_in[7];
    const float* bo = (const float*)d_in[8];
    float* out = (float*)d_out;

    cudaFuncSetAttribute(qkv_kernel, cudaFuncAttributeMaxDynamicSharedMemorySize, SMEM_QKV);
    cudaFuncSetAttribute(out_kernel, cudaFuncAttributeMaxDynamicSharedMemorySize, SMEM_OUT);

    wprep_kernel<<<3, 256>>>(Wq, Wk, Wv);
    qkv_kernel<<<NCTA, 512, SMEM_QKV>>>(x, bq, bk, bv);
    fold_kernel<<<NBR * HEADS, 256>>>(Wo);
    out_kernel<<<NROWS / 64, 256, SMEM_OUT>>>(bo, out);
}